// round 5
// baseline (speedup 1.0000x reference)
#include <cuda_runtime.h>
#include <cuda_fp16.h>
#include <mma.h>
#include <cuda_pipeline.h>
#include <cstdint>

using namespace nvcuda;

constexpr int N  = 512;
constexpr int CZ = 128;
constexpr int CH = 128;
constexpr int M  = N * N;   // 262144

// fp16 scratch: z converted, weights converted, gated activations (channel-major).
__device__ __half g_zh[(size_t)M * CZ];          // 64 MB
__device__ __half g_wh[4 * CH * CZ];             // [ag, ap, bg, bp]
__device__ __half g_a[(size_t)CH * M];           // 64 MB, a[c][m]
__device__ __half g_b[(size_t)CH * M];           // 64 MB, b[c][m]

// ---------------------------------------------------------------------------
// Prepass: fp32 -> fp16 conversions
// ---------------------------------------------------------------------------
__global__ void convert_z_kernel(const float* __restrict__ z)
{
    const size_t n8 = (size_t)M * CZ / 8;
    const size_t stride = (size_t)gridDim.x * blockDim.x;
    for (size_t i = (size_t)blockIdx.x * blockDim.x + threadIdx.x; i < n8; i += stride) {
        float4 v0 = ((const float4*)z)[i * 2];
        float4 v1 = ((const float4*)z)[i * 2 + 1];
        __half2 h0 = __floats2half2_rn(v0.x, v0.y);
        __half2 h1 = __floats2half2_rn(v0.z, v0.w);
        __half2 h2 = __floats2half2_rn(v1.x, v1.y);
        __half2 h3 = __floats2half2_rn(v1.z, v1.w);
        uint4 u;
        u.x = *(unsigned*)&h0; u.y = *(unsigned*)&h1;
        u.z = *(unsigned*)&h2; u.w = *(unsigned*)&h3;
        ((uint4*)g_zh)[i] = u;
    }
}

__global__ void convert_w_kernel(const float* __restrict__ ag, const float* __restrict__ ap,
                                 const float* __restrict__ bg, const float* __restrict__ bp)
{
    int i = blockIdx.x * blockDim.x + threadIdx.x;
    if (i < 4 * CH * CZ) {
        const float* srcs[4] = {ag, ap, bg, bp};
        g_wh[i] = __float2half_rn(srcs[i >> 14][i & (CH * CZ - 1)]);
    }
}

// ---------------------------------------------------------------------------
// Phase 1: projections + gating (fp16 HMMA, fp32 accumulate).
// Block = 128 m-rows x 128 channels, blockIdx.y selects a/b.
// Two GEMM phases: g (gate) -> sigmoid staged in smem -> p (proj) -> epilogue.
// 512 threads, 16 warps in 4x4 layout, warp tile 32x32.
// ---------------------------------------------------------------------------
constexpr int PW = 136;   // smem leading dim (halves / floats); mult of 8

__global__ __launch_bounds__(512, 1)
void proj_kernel(const float* __restrict__ mask,
                 const float* __restrict__ b_ag, const float* __restrict__ b_ap,
                 const float* __restrict__ b_bg, const float* __restrict__ b_bp)
{
    extern __shared__ __align__(16) char smem_raw[];
    __half* zs  = (__half*)smem_raw;                    // [128][PW] halves, 34816 B
    __half* ws  = (__half*)(smem_raw + 34816);          // [128][PW] halves, 34816 B
    float*  sfl = (float*)(smem_raw + 69632);           // col-major [c][r], 69632 B
    float*  pfl = (float*)smem_raw;                     // overlaps zs+ws exactly

    const int  m0   = blockIdx.x * 128;
    const bool is_b = (blockIdx.y != 0);
    const __half* wg = g_wh + (is_b ? 2 : 0) * (CH * CZ);
    const __half* wp = wg + CH * CZ;
    const float* bgp = is_b ? b_bg : b_ag;
    const float* bpp = is_b ? b_bp : b_ap;
    __half* outp = is_b ? g_b : g_a;

    const int tid  = threadIdx.x;
    const int warp = tid >> 5;
    const int wrow = (warp >> 2) * 32;   // 0,32,64,96
    const int wcol = (warp & 3) * 32;    // 0,32,64,96

    // Stage z tile [128 x 128] and gate weights [128 x 128]
    for (int t = tid; t < 128 * 16; t += 512) {
        int r = t >> 4, q = t & 15;
        *(float4*)&zs[r * PW + q * 8] =
            *(const float4*)&g_zh[(size_t)(m0 + r) * CZ + q * 8];
    }
    for (int t = tid; t < 128 * 16; t += 512) {
        int r = t >> 4, q = t & 15;
        *(float4*)&ws[r * PW + q * 8] = *(const float4*)&wg[r * CZ + q * 8];
    }
    __syncthreads();

    wmma::fragment<wmma::accumulator, 16, 16, 16, float> acc[2][2];

    // ---- GEMM 1: gate = z . Wg^T ----
    #pragma unroll
    for (int i = 0; i < 2; i++)
        #pragma unroll
        for (int n = 0; n < 2; n++)
            wmma::fill_fragment(acc[i][n], 0.0f);

    #pragma unroll
    for (int ks = 0; ks < CZ / 16; ks++) {
        wmma::fragment<wmma::matrix_a, 16, 16, 16, __half, wmma::row_major> af[2];
        #pragma unroll
        for (int i = 0; i < 2; i++)
            wmma::load_matrix_sync(af[i], zs + (wrow + i * 16) * PW + ks * 16, PW);
        #pragma unroll
        for (int n = 0; n < 2; n++) {
            wmma::fragment<wmma::matrix_b, 16, 16, 16, __half, wmma::col_major> bf;
            wmma::load_matrix_sync(bf, ws + (wcol + n * 16) * PW + ks * 16, PW);
            #pragma unroll
            for (int i = 0; i < 2; i++)
                wmma::mma_sync(acc[i][n], af[i], bf, acc[i][n]);
        }
    }

    // Stage gate col-major, then sigmoid+bias elementwise
    #pragma unroll
    for (int i = 0; i < 2; i++)
        #pragma unroll
        for (int n = 0; n < 2; n++)
            wmma::store_matrix_sync(sfl + (wcol + n * 16) * PW + (wrow + i * 16),
                                    acc[i][n], PW, wmma::mem_col_major);
    __syncthreads();

    for (int idx = tid; idx < CH * 128; idx += 512) {
        int c = idx >> 7, r = idx & 127;
        float v = sfl[c * PW + r] + bgp[c];
        sfl[c * PW + r] = 1.0f / (1.0f + __expf(-v));
    }
    // Overwrite ws with projection weights (safe: all GEMM-1 reads done at sync above)
    for (int t = tid; t < 128 * 16; t += 512) {
        int r = t >> 4, q = t & 15;
        *(float4*)&ws[r * PW + q * 8] = *(const float4*)&wp[r * CZ + q * 8];
    }
    __syncthreads();

    // ---- GEMM 2: p = z . Wp^T ----
    #pragma unroll
    for (int i = 0; i < 2; i++)
        #pragma unroll
        for (int n = 0; n < 2; n++)
            wmma::fill_fragment(acc[i][n], 0.0f);

    #pragma unroll
    for (int ks = 0; ks < CZ / 16; ks++) {
        wmma::fragment<wmma::matrix_a, 16, 16, 16, __half, wmma::row_major> af[2];
        #pragma unroll
        for (int i = 0; i < 2; i++)
            wmma::load_matrix_sync(af[i], zs + (wrow + i * 16) * PW + ks * 16, PW);
        #pragma unroll
        for (int n = 0; n < 2; n++) {
            wmma::fragment<wmma::matrix_b, 16, 16, 16, __half, wmma::col_major> bf;
            wmma::load_matrix_sync(bf, ws + (wcol + n * 16) * PW + ks * 16, PW);
            #pragma unroll
            for (int i = 0; i < 2; i++)
                wmma::mma_sync(acc[i][n], af[i], bf, acc[i][n]);
        }
    }
    __syncthreads();   // all warps done reading zs/ws before pfl overwrites them

    #pragma unroll
    for (int i = 0; i < 2; i++)
        #pragma unroll
        for (int n = 0; n < 2; n++)
            wmma::store_matrix_sync(pfl + (wcol + n * 16) * PW + (wrow + i * 16),
                                    acc[i][n], PW, wmma::mem_col_major);
    __syncthreads();

    // Epilogue: out[c][m0+r] = mask * sigmoid(g+bg) * (p+bp), fp16, half2 stores
    for (int i = tid; i < CH * 64; i += 512) {
        int c = i >> 6, r = (i & 63) * 2;
        float s0 = sfl[c * PW + r],     s1 = sfl[c * PW + r + 1];
        float p0 = pfl[c * PW + r] + bpp[c];
        float p1 = pfl[c * PW + r + 1] + bpp[c];
        float k0 = mask[m0 + r], k1 = mask[m0 + r + 1];
        __half2 o = __floats2half2_rn(k0 * s0 * p0, k1 * s1 * p1);
        *(__half2*)&outp[(size_t)c * M + m0 + r] = o;
    }
}

// ---------------------------------------------------------------------------
// Phase 2: per-channel out[c] = A_c @ B_c^T, fp16 inputs, fp32 accumulate.
// 128x128 tile, K-chunks of 64, cp.async double-buffered. 256 threads,
// warp tile 32x64. 2 blocks/SM.
// ---------------------------------------------------------------------------
constexpr int TW     = 72;                 // smem leading dim (halves)
constexpr int TBUF   = 128 * TW;           // halves per matrix per buffer

__global__ __launch_bounds__(256, 2)
void tri_kernel(float* __restrict__ out)
{
    extern __shared__ __align__(16) __half tsm[];
    __half* As = tsm;                  // [2][TBUF]
    __half* Bs = tsm + 2 * TBUF;       // [2][TBUF]

    const int c  = blockIdx.z;
    const int bi = blockIdx.x * 128;
    const int bj = blockIdx.y * 128;
    const __half* A = g_a + (size_t)c * M + (size_t)bi * N;
    const __half* B = g_b + (size_t)c * M + (size_t)bj * N;

    const int tid  = threadIdx.x;
    const int warp = tid >> 5;
    const int wrow = (warp >> 1) * 32;   // 0,32,64,96
    const int wcol = (warp & 1) * 64;    // 0,64

    wmma::fragment<wmma::accumulator, 16, 16, 16, float> acc[2][4];
    #pragma unroll
    for (int i = 0; i < 2; i++)
        #pragma unroll
        for (int n = 0; n < 4; n++)
            wmma::fill_fragment(acc[i][n], 0.0f);

    auto stage = [&](int buf, int kc) {
        #pragma unroll
        for (int t = tid; t < 1024; t += 256) {
            int r = t >> 3, q = t & 7;
            __pipeline_memcpy_async(&As[buf * TBUF + r * TW + q * 8],
                                    &A[(size_t)r * N + kc + q * 8], 16);
        }
        #pragma unroll
        for (int t = tid; t < 1024; t += 256) {
            int r = t >> 3, q = t & 7;
            __pipeline_memcpy_async(&Bs[buf * TBUF + r * TW + q * 8],
                                    &B[(size_t)r * N + kc + q * 8], 16);
        }
        __pipeline_commit();
    };

    stage(0, 0);
    for (int ch = 0; ch < N / 64; ch++) {
        if (ch + 1 < N / 64) stage((ch + 1) & 1, (ch + 1) * 64);
        if (ch + 1 < N / 64) __pipeline_wait_prior(1);
        else                 __pipeline_wait_prior(0);
        __syncthreads();

        const __half* a0 = As + (ch & 1) * TBUF;
        const __half* b0 = Bs + (ch & 1) * TBUF;
        #pragma unroll
        for (int ks = 0; ks < 4; ks++) {
            wmma::fragment<wmma::matrix_a, 16, 16, 16, __half, wmma::row_major> af[2];
            #pragma unroll
            for (int i = 0; i < 2; i++)
                wmma::load_matrix_sync(af[i], a0 + (wrow + i * 16) * TW + ks * 16, TW);
            #pragma unroll
            for (int n = 0; n < 4; n++) {
                wmma::fragment<wmma::matrix_b, 16, 16, 16, __half, wmma::col_major> bf;
                wmma::load_matrix_sync(bf, b0 + (wcol + n * 16) * TW + ks * 16, TW);
                #pragma unroll
                for (int i = 0; i < 2; i++)
                    wmma::mma_sync(acc[i][n], af[i], bf, acc[i][n]);
            }
        }
        __syncthreads();
    }

    float* outc = out + (size_t)c * M;
    #pragma unroll
    for (int i = 0; i < 2; i++)
        #pragma unroll
        for (int n = 0; n < 4; n++)
            wmma::store_matrix_sync(
                outc + (size_t)(bi + wrow + i * 16) * N + (bj + wcol + n * 16),
                acc[i][n], N, wmma::mem_row_major);
}

// ---------------------------------------------------------------------------
// kernel_launch
// ---------------------------------------------------------------------------
extern "C" void kernel_launch(void* const* d_in, const int* in_sizes, int n_in,
                              void* d_out, int out_size)
{
    const float* z    = (const float*)d_in[0];
    const float* mask = (const float*)d_in[1];
    const float* w_ag = (const float*)d_in[2];
    const float* b_ag = (const float*)d_in[3];
    const float* w_ap = (const float*)d_in[4];
    const float* b_ap = (const float*)d_in[5];
    const float* w_bg = (const float*)d_in[6];
    const float* b_bg = (const float*)d_in[7];
    const float* w_bp = (const float*)d_in[8];
    const float* b_bp = (const float*)d_in[9];
    float* out = (float*)d_out;

    cudaFuncSetAttribute(proj_kernel, cudaFuncAttributeMaxDynamicSharedMemorySize, 139264);
    cudaFuncSetAttribute(tri_kernel,  cudaFuncAttributeMaxDynamicSharedMemorySize, 4 * TBUF * 2);

    convert_z_kernel<<<2048, 256>>>(z);
    convert_w_kernel<<<(4 * CH * CZ + 255) / 256, 256>>>(w_ag, w_ap, w_bg, w_bp);
    proj_kernel<<<dim3(M / 128, 2), 512, 139264>>>(mask, b_ag, b_ap, b_bg, b_bp);
    tri_kernel<<<dim3(N / 128, N / 128, CH), 256, 4 * TBUF * 2>>>(out);
}

// round 6
// speedup vs baseline: 1.0045x; 1.0045x over previous
#include <cuda_runtime.h>
#include <cuda_fp16.h>
#include <mma.h>
#include <cuda_pipeline.h>
#include <cstdint>

using namespace nvcuda;

constexpr int N  = 512;
constexpr int CZ = 128;
constexpr int CH = 128;
constexpr int M  = N * N;   // 262144

// fp16 scratch: z converted, weights converted, gated activations (channel-major).
__device__ __half g_zh[(size_t)M * CZ];          // 64 MB
__device__ __half g_wh[4 * CH * CZ];             // [ag, ap, bg, bp]
__device__ __half g_a[(size_t)CH * M];           // 64 MB, a[c][m]
__device__ __half g_b[(size_t)CH * M];           // 64 MB, b[c][m]

// ---------------------------------------------------------------------------
// Prepass: fp32 -> fp16 conversions
// ---------------------------------------------------------------------------
__global__ void convert_z_kernel(const float* __restrict__ z)
{
    const size_t n8 = (size_t)M * CZ / 8;
    const size_t stride = (size_t)gridDim.x * blockDim.x;
    for (size_t i = (size_t)blockIdx.x * blockDim.x + threadIdx.x; i < n8; i += stride) {
        float4 v0 = ((const float4*)z)[i * 2];
        float4 v1 = ((const float4*)z)[i * 2 + 1];
        __half2 h0 = __floats2half2_rn(v0.x, v0.y);
        __half2 h1 = __floats2half2_rn(v0.z, v0.w);
        __half2 h2 = __floats2half2_rn(v1.x, v1.y);
        __half2 h3 = __floats2half2_rn(v1.z, v1.w);
        uint4 u;
        u.x = *(unsigned*)&h0; u.y = *(unsigned*)&h1;
        u.z = *(unsigned*)&h2; u.w = *(unsigned*)&h3;
        ((uint4*)g_zh)[i] = u;
    }
}

__global__ void convert_w_kernel(const float* __restrict__ ag, const float* __restrict__ ap,
                                 const float* __restrict__ bg, const float* __restrict__ bp)
{
    int i = blockIdx.x * blockDim.x + threadIdx.x;
    if (i < 4 * CH * CZ) {
        const float* srcs[4] = {ag, ap, bg, bp};
        g_wh[i] = __float2half_rn(srcs[i >> 14][i & (CH * CZ - 1)]);
    }
}

// ---------------------------------------------------------------------------
// Phase 1: projections + gating (fp16 HMMA, fp32 accumulate).
// Block = 128 m-rows x 128 channels, blockIdx.y selects a/b.
// Two GEMM phases: g (gate) -> sigmoid staged in smem -> p (proj) -> epilogue.
// 512 threads, 16 warps in 4x4 layout, warp tile 32x32.
// ---------------------------------------------------------------------------
constexpr int PW = 136;   // smem leading dim (halves / floats); mult of 8

__global__ __launch_bounds__(512, 1)
void proj_kernel(const float* __restrict__ mask,
                 const float* __restrict__ b_ag, const float* __restrict__ b_ap,
                 const float* __restrict__ b_bg, const float* __restrict__ b_bp)
{
    extern __shared__ __align__(16) char smem_raw[];
    __half* zs  = (__half*)smem_raw;                    // [128][PW] halves, 34816 B
    __half* ws  = (__half*)(smem_raw + 34816);          // [128][PW] halves, 34816 B
    float*  sfl = (float*)(smem_raw + 69632);           // col-major [c][r], 69632 B
    float*  pfl = (float*)smem_raw;                     // overlaps zs+ws exactly

    const int  m0   = blockIdx.x * 128;
    const bool is_b = (blockIdx.y != 0);
    const __half* wg = g_wh + (is_b ? 2 : 0) * (CH * CZ);
    const __half* wp = wg + CH * CZ;
    const float* bgp = is_b ? b_bg : b_ag;
    const float* bpp = is_b ? b_bp : b_ap;
    __half* outp = is_b ? g_b : g_a;

    const int tid  = threadIdx.x;
    const int warp = tid >> 5;
    const int wrow = (warp >> 2) * 32;   // 0,32,64,96
    const int wcol = (warp & 3) * 32;    // 0,32,64,96

    // Stage z tile [128 x 128] and gate weights [128 x 128]
    for (int t = tid; t < 128 * 16; t += 512) {
        int r = t >> 4, q = t & 15;
        *(float4*)&zs[r * PW + q * 8] =
            *(const float4*)&g_zh[(size_t)(m0 + r) * CZ + q * 8];
    }
    for (int t = tid; t < 128 * 16; t += 512) {
        int r = t >> 4, q = t & 15;
        *(float4*)&ws[r * PW + q * 8] = *(const float4*)&wg[r * CZ + q * 8];
    }
    __syncthreads();

    wmma::fragment<wmma::accumulator, 16, 16, 16, float> acc[2][2];

    // ---- GEMM 1: gate = z . Wg^T ----
    #pragma unroll
    for (int i = 0; i < 2; i++)
        #pragma unroll
        for (int n = 0; n < 2; n++)
            wmma::fill_fragment(acc[i][n], 0.0f);

    #pragma unroll
    for (int ks = 0; ks < CZ / 16; ks++) {
        wmma::fragment<wmma::matrix_a, 16, 16, 16, __half, wmma::row_major> af[2];
        #pragma unroll
        for (int i = 0; i < 2; i++)
            wmma::load_matrix_sync(af[i], zs + (wrow + i * 16) * PW + ks * 16, PW);
        #pragma unroll
        for (int n = 0; n < 2; n++) {
            wmma::fragment<wmma::matrix_b, 16, 16, 16, __half, wmma::col_major> bf;
            wmma::load_matrix_sync(bf, ws + (wcol + n * 16) * PW + ks * 16, PW);
            #pragma unroll
            for (int i = 0; i < 2; i++)
                wmma::mma_sync(acc[i][n], af[i], bf, acc[i][n]);
        }
    }

    // Stage gate col-major, then sigmoid+bias elementwise
    #pragma unroll
    for (int i = 0; i < 2; i++)
        #pragma unroll
        for (int n = 0; n < 2; n++)
            wmma::store_matrix_sync(sfl + (wcol + n * 16) * PW + (wrow + i * 16),
                                    acc[i][n], PW, wmma::mem_col_major);
    __syncthreads();

    for (int idx = tid; idx < CH * 128; idx += 512) {
        int c = idx >> 7, r = idx & 127;
        float v = sfl[c * PW + r] + bgp[c];
        sfl[c * PW + r] = 1.0f / (1.0f + __expf(-v));
    }
    // Overwrite ws with projection weights (safe: all GEMM-1 reads done at sync above)
    for (int t = tid; t < 128 * 16; t += 512) {
        int r = t >> 4, q = t & 15;
        *(float4*)&ws[r * PW + q * 8] = *(const float4*)&wp[r * CZ + q * 8];
    }
    __syncthreads();

    // ---- GEMM 2: p = z . Wp^T ----
    #pragma unroll
    for (int i = 0; i < 2; i++)
        #pragma unroll
        for (int n = 0; n < 2; n++)
            wmma::fill_fragment(acc[i][n], 0.0f);

    #pragma unroll
    for (int ks = 0; ks < CZ / 16; ks++) {
        wmma::fragment<wmma::matrix_a, 16, 16, 16, __half, wmma::row_major> af[2];
        #pragma unroll
        for (int i = 0; i < 2; i++)
            wmma::load_matrix_sync(af[i], zs + (wrow + i * 16) * PW + ks * 16, PW);
        #pragma unroll
        for (int n = 0; n < 2; n++) {
            wmma::fragment<wmma::matrix_b, 16, 16, 16, __half, wmma::col_major> bf;
            wmma::load_matrix_sync(bf, ws + (wcol + n * 16) * PW + ks * 16, PW);
            #pragma unroll
            for (int i = 0; i < 2; i++)
                wmma::mma_sync(acc[i][n], af[i], bf, acc[i][n]);
        }
    }
    __syncthreads();   // all warps done reading zs/ws before pfl overwrites them

    #pragma unroll
    for (int i = 0; i < 2; i++)
        #pragma unroll
        for (int n = 0; n < 2; n++)
            wmma::store_matrix_sync(pfl + (wcol + n * 16) * PW + (wrow + i * 16),
                                    acc[i][n], PW, wmma::mem_col_major);
    __syncthreads();

    // Epilogue: out[c][m0+r] = mask * sigmoid(g+bg) * (p+bp), fp16, half2 stores
    for (int i = tid; i < CH * 64; i += 512) {
        int c = i >> 6, r = (i & 63) * 2;
        float s0 = sfl[c * PW + r],     s1 = sfl[c * PW + r + 1];
        float p0 = pfl[c * PW + r] + bpp[c];
        float p1 = pfl[c * PW + r + 1] + bpp[c];
        float k0 = mask[m0 + r], k1 = mask[m0 + r + 1];
        __half2 o = __floats2half2_rn(k0 * s0 * p0, k1 * s1 * p1);
        *(__half2*)&outp[(size_t)c * M + m0 + r] = o;
    }
}

// ---------------------------------------------------------------------------
// Phase 2: per-channel out[c] = A_c @ B_c^T, fp16 inputs, fp32 accumulate.
// 128x128 tile, K-chunks of 64, cp.async double-buffered. 256 threads,
// warp tile 32x64. 2 blocks/SM.
// ---------------------------------------------------------------------------
constexpr int TW     = 72;                 // smem leading dim (halves)
constexpr int TBUF   = 128 * TW;           // halves per matrix per buffer

__global__ __launch_bounds__(256, 2)
void tri_kernel(float* __restrict__ out)
{
    extern __shared__ __align__(16) __half tsm[];
    __half* As = tsm;                  // [2][TBUF]
    __half* Bs = tsm + 2 * TBUF;       // [2][TBUF]

    const int c  = blockIdx.z;
    const int bi = blockIdx.x * 128;
    const int bj = blockIdx.y * 128;
    const __half* A = g_a + (size_t)c * M + (size_t)bi * N;
    const __half* B = g_b + (size_t)c * M + (size_t)bj * N;

    const int tid  = threadIdx.x;
    const int warp = tid >> 5;
    const int wrow = (warp >> 1) * 32;   // 0,32,64,96
    const int wcol = (warp & 1) * 64;    // 0,64

    wmma::fragment<wmma::accumulator, 16, 16, 16, float> acc[2][4];
    #pragma unroll
    for (int i = 0; i < 2; i++)
        #pragma unroll
        for (int n = 0; n < 4; n++)
            wmma::fill_fragment(acc[i][n], 0.0f);

    auto stage = [&](int buf, int kc) {
        #pragma unroll
        for (int t = tid; t < 1024; t += 256) {
            int r = t >> 3, q = t & 7;
            __pipeline_memcpy_async(&As[buf * TBUF + r * TW + q * 8],
                                    &A[(size_t)r * N + kc + q * 8], 16);
        }
        #pragma unroll
        for (int t = tid; t < 1024; t += 256) {
            int r = t >> 3, q = t & 7;
            __pipeline_memcpy_async(&Bs[buf * TBUF + r * TW + q * 8],
                                    &B[(size_t)r * N + kc + q * 8], 16);
        }
        __pipeline_commit();
    };

    stage(0, 0);
    for (int ch = 0; ch < N / 64; ch++) {
        if (ch + 1 < N / 64) stage((ch + 1) & 1, (ch + 1) * 64);
        if (ch + 1 < N / 64) __pipeline_wait_prior(1);
        else                 __pipeline_wait_prior(0);
        __syncthreads();

        const __half* a0 = As + (ch & 1) * TBUF;
        const __half* b0 = Bs + (ch & 1) * TBUF;
        #pragma unroll
        for (int ks = 0; ks < 4; ks++) {
            wmma::fragment<wmma::matrix_a, 16, 16, 16, __half, wmma::row_major> af[2];
            #pragma unroll
            for (int i = 0; i < 2; i++)
                wmma::load_matrix_sync(af[i], a0 + (wrow + i * 16) * TW + ks * 16, TW);
            #pragma unroll
            for (int n = 0; n < 4; n++) {
                wmma::fragment<wmma::matrix_b, 16, 16, 16, __half, wmma::col_major> bf;
                wmma::load_matrix_sync(bf, b0 + (wcol + n * 16) * TW + ks * 16, TW);
                #pragma unroll
                for (int i = 0; i < 2; i++)
                    wmma::mma_sync(acc[i][n], af[i], bf, acc[i][n]);
            }
        }
        __syncthreads();
    }

    float* outc = out + (size_t)c * M;
    #pragma unroll
    for (int i = 0; i < 2; i++)
        #pragma unroll
        for (int n = 0; n < 4; n++)
            wmma::store_matrix_sync(
                outc + (size_t)(bi + wrow + i * 16) * N + (bj + wcol + n * 16),
                acc[i][n], N, wmma::mem_row_major);
}

// ---------------------------------------------------------------------------
// kernel_launch
// ---------------------------------------------------------------------------
extern "C" void kernel_launch(void* const* d_in, const int* in_sizes, int n_in,
                              void* d_out, int out_size)
{
    const float* z    = (const float*)d_in[0];
    const float* mask = (const float*)d_in[1];
    const float* w_ag = (const float*)d_in[2];
    const float* b_ag = (const float*)d_in[3];
    const float* w_ap = (const float*)d_in[4];
    const float* b_ap = (const float*)d_in[5];
    const float* w_bg = (const float*)d_in[6];
    const float* b_bg = (const float*)d_in[7];
    const float* w_bp = (const float*)d_in[8];
    const float* b_bp = (const float*)d_in[9];
    float* out = (float*)d_out;

    cudaFuncSetAttribute(proj_kernel, cudaFuncAttributeMaxDynamicSharedMemorySize, 139264);
    cudaFuncSetAttribute(tri_kernel,  cudaFuncAttributeMaxDynamicSharedMemorySize, 4 * TBUF * 2);

    convert_z_kernel<<<2048, 256>>>(z);
    convert_w_kernel<<<(4 * CH * CZ + 255) / 256, 256>>>(w_ag, w_ap, w_bg, w_bp);
    proj_kernel<<<dim3(M / 128, 2), 512, 139264>>>(mask, b_ag, b_ap, b_bg, b_bp);
    tri_kernel<<<dim3(N / 128, N / 128, CH), 256, 4 * TBUF * 2>>>(out);
}